// round 14
// baseline (speedup 1.0000x reference)
#include <cuda_runtime.h>
#include <cstdint>

#define B_ 4
#define S_ 2048
#define E_ 1024
#define H_ 16
#define D_ 64
#define LN_EPS 1e-5f
#define LR 0.1f
#define INV64 0.015625f
#define C_GRAD (2.0f / 4096.0f)

#define N_WORKERS 296
// queue: [0,576) half qkv tiles (chunks 0-2, N-split); [576,1824) full qkv
// (chunks 3-15); [1824,2336) gate; [2336,2400) post; [2400,2912) gemm2
#define NT_HALF 576
#define NT_QKV  1824
#define NT_G1   2336
#define NT_POST 2400
#define NT_ALL  2912

typedef unsigned long long ull;

__device__ float g_q[S_ * B_ * E_];
__device__ float g_k[S_ * B_ * E_];
__device__ float g_v[S_ * B_ * E_];
__device__ float g_gate[B_ * S_ * E_];
__device__ float g_scan[S_ * B_ * E_];
__device__ float g_y[B_ * S_ * E_];
__device__ int   g_ready[16];       // split chunks: target 192; else 96
__device__ int   g_gate_ready[16];
__device__ int   g_scan_done[16];
__device__ int   g_post_done[64];
__device__ int   g_tile;
__device__ int   g_nscan;
__device__ int   g_smids[16];

__device__ __forceinline__ int ready_tgt(int c) { return (c < 3) ? 192 : 96; }

struct __align__(16) ScanSmem {
    float ks[2][B_][D_], ts[2][B_][D_], pt[2][B_][D_];
    float d1h[B_][D_], d1x[2][B_][D_], d1p[2][B_][D_];
    float d2h[B_][D_], d2x[B_][D_], d2p[B_][D_];
    float z2s[B_][D_], dsum[B_][D_];
    float Ms[B_][B_];
};
struct __align__(16) WorkSmem { float As[2][8][128]; float Bs[2][8][128]; };
union SmemU { ScanSmem sc; WorkSmem wk; };

__device__ __forceinline__ void bfly2(float& a, float& b)
{
#pragma unroll
    for (int o = 16; o > 0; o >>= 1) {
        a += __shfl_xor_sync(0xffffffffu, a, o);
        b += __shfl_xor_sync(0xffffffffu, b, o);
    }
}
__device__ __forceinline__ void bfly4(float& a, float& b, float& c, float& d)
{
#pragma unroll
    for (int o = 16; o > 0; o >>= 1) {
        a += __shfl_xor_sync(0xffffffffu, a, o);
        b += __shfl_xor_sync(0xffffffffu, b, o);
        c += __shfl_xor_sync(0xffffffffu, c, o);
        d += __shfl_xor_sync(0xffffffffu, d, o);
    }
}
__device__ __forceinline__ void wait_cnt(int* p, int target)
{
    if (*(volatile int*)p < target) {
        while (*(volatile int*)p < target) __nanosleep(256);
    }
    __threadfence();
}
__device__ __forceinline__ unsigned my_smid()
{
    unsigned s; asm("mov.u32 %0, %%smid;" : "=r"(s)); return s;
}
__device__ __forceinline__ float gelu_t(float x)
{
    float t = 0.7978845608028654f * (x + 0.044715f * x * x * x);
    return 0.5f * x * (1.0f + tanhf(t));
}

#define BAR_A()    asm volatile("bar.sync 1, 128;" ::: "memory")
#define BAR_B()    asm volatile("bar.sync 2, 128;" ::: "memory")
#define BAR_FULL() asm volatile("bar.sync 0, 256;" ::: "memory")

// ---------------------------------------------------------------------------
__device__ void worker_loop(const float* __restrict__ x,
                            const float* __restrict__ Wq, const float* __restrict__ Wk,
                            const float* __restrict__ Wv, const float* __restrict__ Wg,
                            const float* __restrict__ Wo,
                            const float* __restrict__ post_g, const float* __restrict__ post_b,
                            float* __restrict__ C,
                            float (&As)[2][8][128], float (&Bs)[2][8][128],
                            int& s_tile)
{
    const int tid = threadIdx.x;
    const int lm = tid >> 1, lk = (tid & 1) * 4;
    const int tm = (tid >> 4) * 8, tn = (tid & 15) * 8;
    const int warp = tid >> 5, lane = tid & 31;

    for (;;) {
        if (tid == 0) s_tile = atomicAdd(&g_tile, 1);
        __syncthreads();
        const int gid = s_tile;
        if (gid >= NT_ALL) break;

        if (gid < NT_HALF) {
            // ======= half qkv tile (chunks 0-2, N-split: 128 x 64) =======
            const int t2 = gid >> 1, nh = gid & 1;
            const int bmp = t2 / 24, bn2 = t2 % 24;
            const int chunk = bmp >> 2, b = bmp & 3;
            const int m0 = b * 2048 + chunk * 128;
            const int nbase = bn2 * 128;
            const int p2 = nbase >> 10;
            const float* Bmat = (p2 == 0) ? Wq : (p2 == 1) ? Wk : Wv;
            const int frow = (nbase & 1023) + nh * 64;
            const float* ArowH = x + (size_t)(m0 + lm) * 1024 + lk;
            const float* BrowH = Bmat + (size_t)(frow + lm) * 1024 + lk; // tid<128
            const int tmH = (tid >> 3) * 4;
            const int tnH = (tid & 7) * 8;

            ull acc[4][4];
#pragma unroll
            for (int i = 0; i < 4; i++)
#pragma unroll
                for (int j = 0; j < 4; j++) acc[i][j] = 0ull;

            {
                float4 a4 = *(const float4*)(ArowH);
                As[0][lk+0][lm] = a4.x; As[0][lk+1][lm] = a4.y;
                As[0][lk+2][lm] = a4.z; As[0][lk+3][lm] = a4.w;
                if (tid < 128) {
                    float4 b4 = *(const float4*)(BrowH);
                    Bs[0][lk+0][lm] = b4.x; Bs[0][lk+1][lm] = b4.y;
                    Bs[0][lk+2][lm] = b4.z; Bs[0][lk+3][lm] = b4.w;
                }
            }
            __syncthreads();

            for (int t = 0; t < 128; t++) {
                const int cur = t & 1, nxt = cur ^ 1;
                float4 a4, b4;
                const bool more = (t + 1 < 128);
                if (more) {
                    a4 = *(const float4*)(ArowH + (t + 1) * 8);
                    if (tid < 128) b4 = *(const float4*)(BrowH + (t + 1) * 8);
                }
#pragma unroll
                for (int kk = 0; kk < 8; kk++) {
                    ull b2[4];
#pragma unroll
                    for (int j = 0; j < 4; j++)
                        b2[j] = *(const ull*)&Bs[cur][kk][tnH + 2*j];
                    float4 av = *(const float4*)&As[cur][kk][tmH];
                    ull ax0, ax1, ax2, ax3;
                    asm("mov.b64 %0, {%1, %1};" : "=l"(ax0) : "f"(av.x));
                    asm("mov.b64 %0, {%1, %1};" : "=l"(ax1) : "f"(av.y));
                    asm("mov.b64 %0, {%1, %1};" : "=l"(ax2) : "f"(av.z));
                    asm("mov.b64 %0, {%1, %1};" : "=l"(ax3) : "f"(av.w));
#pragma unroll
                    for (int j = 0; j < 4; j++) {
                        asm("fma.rn.f32x2 %0, %1, %2, %0;" : "+l"(acc[0][j]) : "l"(ax0), "l"(b2[j]));
                        asm("fma.rn.f32x2 %0, %1, %2, %0;" : "+l"(acc[1][j]) : "l"(ax1), "l"(b2[j]));
                        asm("fma.rn.f32x2 %0, %1, %2, %0;" : "+l"(acc[2][j]) : "l"(ax2), "l"(b2[j]));
                        asm("fma.rn.f32x2 %0, %1, %2, %0;" : "+l"(acc[3][j]) : "l"(ax3), "l"(b2[j]));
                    }
                }
                if (more) {
                    As[nxt][lk+0][lm] = a4.x; As[nxt][lk+1][lm] = a4.y;
                    As[nxt][lk+2][lm] = a4.z; As[nxt][lk+3][lm] = a4.w;
                    if (tid < 128) {
                        Bs[nxt][lk+0][lm] = b4.x; Bs[nxt][lk+1][lm] = b4.y;
                        Bs[nxt][lk+2][lm] = b4.z; Bs[nxt][lk+3][lm] = b4.w;
                    }
                }
                __syncthreads();
            }

            const int f = frow + tnH;
#pragma unroll
            for (int i = 0; i < 4; i++) {
                int s = chunk * 128 + tmH + i;
                float* dstf = (p2 == 0 ? g_q : p2 == 1 ? g_k : g_v)
                              + (size_t)(s * B_ + b) * 1024 + f;
                ull* dst = (ull*)dstf;
#pragma unroll
                for (int j = 0; j < 4; j++) dst[j] = acc[i][j];
            }
            __threadfence();
            __syncthreads();
            if (tid == 0) atomicAdd(&g_ready[chunk], 1);
            continue;
        }

        if (gid >= NT_G1 && gid < NT_POST) {
            // ---------------- post tile ----------------
            const int t = gid - NT_G1;
            const int chunk = t >> 2, b = t & 3;
            wait_cnt(&g_scan_done[chunk], 16);
            wait_cnt(&g_gate_ready[chunk], 32);
            for (int r = warp; r < 128; r += 8) {
                const int s = chunk * 128 + r;
                const float4* in = (const float4*)(g_scan + (size_t)(s * B_ + b) * E_);
                const float4* gp = (const float4*)(g_gate + (size_t)(b * 2048 + s) * E_);
                float4* out = (float4*)(g_y + (size_t)(b * 2048 + s) * E_);
                float4 v[8]; float sum = 0.f, sq = 0.f;
#pragma unroll
                for (int i = 0; i < 8; i++) {
                    v[i] = in[lane + 32 * i];
                    sum += v[i].x + v[i].y + v[i].z + v[i].w;
                    sq  += v[i].x*v[i].x + v[i].y*v[i].y + v[i].z*v[i].z + v[i].w*v[i].w;
                }
                bfly2(sum, sq);
                float mu = sum * (1.0f / 1024.0f);
                float rs = rsqrtf(sq * (1.0f / 1024.0f) - mu * mu + LN_EPS);
#pragma unroll
                for (int i = 0; i < 8; i++) {
                    float4 pg = ((const float4*)post_g)[lane + 32 * i];
                    float4 pb = ((const float4*)post_b)[lane + 32 * i];
                    float4 gg = gp[lane + 32 * i];
                    float4 o;
                    o.x = gelu_t(gg.x) * ((v[i].x - mu) * rs * pg.x + pb.x);
                    o.y = gelu_t(gg.y) * ((v[i].y - mu) * rs * pg.y + pb.y);
                    o.z = gelu_t(gg.z) * ((v[i].z - mu) * rs * pg.z + pb.z);
                    o.w = gelu_t(gg.w) * ((v[i].w - mu) * rs * pg.w + pb.w);
                    out[lane + 32 * i] = o;
                }
            }
            __threadfence();
            __syncthreads();
            if (tid == 0) atomicAdd(&g_post_done[chunk * 4 + b], 1);
            continue;
        }

        // ---------------- full gemm tile (128x128) ----------------
        const float *Arow, *Brow;
        int chunk, b, bn, p, m0;
        if (gid < NT_QKV) {
            int t = gid - 288;                       // full qkv, chunks 3-15
            int bmp = t / 24; bn = t % 24;
            chunk = bmp >> 2; b = bmp & 3;
            m0 = b * 2048 + chunk * 128;
            const int nbase = bn * 128;
            p = nbase >> 10;
            const float* Bmat = (p == 0) ? Wq : (p == 1) ? Wk : Wv;
            Arow = x + (size_t)(m0 + lm) * 1024 + lk;
            Brow = Bmat + (size_t)((nbase & 1023) + lm) * 1024 + lk;
        } else if (gid < NT_G1) {
            int g2 = gid - NT_QKV;                   // gate
            int bmp = g2 >> 3; bn = 24 + (g2 & 7);
            chunk = bmp >> 2; b = bmp & 3;
            m0 = b * 2048 + chunk * 128;
            p = 3;
            Arow = x + (size_t)(m0 + lm) * 1024 + lk;
            Brow = Wg + (size_t)(((bn * 128) & 1023) + lm) * 1024 + lk;
        } else {
            int g2 = gid - NT_POST;                  // gemm2
            chunk = g2 >> 5;
            int rr = g2 & 31;
            b = rr >> 3; bn = rr & 7;
            p = 4;
            m0 = b * 2048 + chunk * 128;
            wait_cnt(&g_post_done[chunk * 4 + b], 1);
            Arow = g_y + (size_t)(m0 + lm) * 1024 + lk;
            Brow = Wo + (size_t)(bn * 128 + lm) * 1024 + lk;
        }

        ull acc[8][4];
#pragma unroll
        for (int i = 0; i < 8; i++)
#pragma unroll
            for (int j = 0; j < 4; j++) acc[i][j] = 0ull;

        {
            float4 a4 = *(const float4*)(Arow);
            float4 b4 = *(const float4*)(Brow);
            As[0][lk+0][lm] = a4.x; As[0][lk+1][lm] = a4.y;
            As[0][lk+2][lm] = a4.z; As[0][lk+3][lm] = a4.w;
            Bs[0][lk+0][lm] = b4.x; Bs[0][lk+1][lm] = b4.y;
            Bs[0][lk+2][lm] = b4.z; Bs[0][lk+3][lm] = b4.w;
        }
        __syncthreads();

        for (int t = 0; t < 128; t++) {
            const int cur = t & 1, nxt = cur ^ 1;
            float4 a4, b4;
            const bool more = (t + 1 < 128);
            if (more) {
                a4 = *(const float4*)(Arow + (t + 1) * 8);
                b4 = *(const float4*)(Brow + (t + 1) * 8);
            }
#pragma unroll
            for (int kk = 0; kk < 8; kk++) {
                ull b2[4];
#pragma unroll
                for (int j = 0; j < 4; j++)
                    b2[j] = *(const ull*)&Bs[cur][kk][tn + 2*j];
                float2 a2[4];
#pragma unroll
                for (int i = 0; i < 4; i++)
                    a2[i] = *(const float2*)&As[cur][kk][tm + 2*i];
#pragma unroll
                for (int i = 0; i < 4; i++) {
                    ull axlo, axhi;
                    asm("mov.b64 %0, {%1, %1};" : "=l"(axlo) : "f"(a2[i].x));
                    asm("mov.b64 %0, {%1, %1};" : "=l"(axhi) : "f"(a2[i].y));
#pragma unroll
                    for (int j = 0; j < 4; j++) {
                        asm("fma.rn.f32x2 %0, %1, %2, %0;"
                            : "+l"(acc[2*i][j]) : "l"(axlo), "l"(b2[j]));
                        asm("fma.rn.f32x2 %0, %1, %2, %0;"
                            : "+l"(acc[2*i+1][j]) : "l"(axhi), "l"(b2[j]));
                    }
                }
            }
            if (more) {
                As[nxt][lk+0][lm] = a4.x; As[nxt][lk+1][lm] = a4.y;
                As[nxt][lk+2][lm] = a4.z; As[nxt][lk+3][lm] = a4.w;
                Bs[nxt][lk+0][lm] = b4.x; Bs[nxt][lk+1][lm] = b4.y;
                Bs[nxt][lk+2][lm] = b4.z; Bs[nxt][lk+3][lm] = b4.w;
            }
            __syncthreads();
        }

        if (p == 4) {
#pragma unroll
            for (int i = 0; i < 8; i++) {
                int m = m0 + tm + i;
                ull* crow = (ull*)(C + (size_t)m * 1024 + bn * 128 + tn);
#pragma unroll
                for (int j = 0; j < 4; j++) crow[j] = acc[i][j];
            }
            __syncthreads();
        } else {
            const int f = ((bn * 128) & 1023) + tn;
#pragma unroll
            for (int i = 0; i < 8; i++) {
                int s = chunk * 128 + tm + i;
                float* dstf = (p == 3)
                    ? g_gate + (size_t)(b * 2048 + s) * 1024 + f
                    : (p == 0 ? g_q : p == 1 ? g_k : g_v) + (size_t)(s * B_ + b) * 1024 + f;
                ull* dst = (ull*)dstf;
#pragma unroll
                for (int j = 0; j < 4; j++) dst[j] = acc[i][j];
            }
            __threadfence();
            __syncthreads();
            if (tid == 0) {
                if (p < 3) atomicAdd(&g_ready[chunk], 1);
                else       atomicAdd(&g_gate_ready[chunk], 1);
            }
        }
    }
}

// ---------------------------------------------------------------------------
// Fused: blocks 0-15 = TTT scan (3 barriers/token); blocks 16+ = workers.
// ---------------------------------------------------------------------------
__global__ void __launch_bounds__(256, 2)
fused_kernel(const float* __restrict__ x,
             const float* __restrict__ Wq, const float* __restrict__ Wk,
             const float* __restrict__ Wv, const float* __restrict__ Wg,
             const float* __restrict__ Wo,
             const float* __restrict__ fw_W, const float* __restrict__ fw_b,
             const float* __restrict__ fw_g, const float* __restrict__ fw_bl,
             const float* __restrict__ ttt_g, const float* __restrict__ ttt_b,
             const float* __restrict__ post_g, const float* __restrict__ post_b,
             float* __restrict__ C)
{
    __shared__ SmemU U;
    __shared__ int s_flag, s_tile;
    const int tid = threadIdx.x;

    if (blockIdx.x >= 16) {
        if (tid == 0) {
            unsigned smid = my_smid();
            int it = 0;
            while (*(volatile int*)&g_nscan < 16 && it < 50000) { __nanosleep(128); it++; }
            __threadfence();
            int excl = 0;
            if (*(volatile int*)&g_nscan >= 16) {
#pragma unroll
                for (int i = 0; i < 16; i++)
                    if (g_smids[i] == (int)smid) excl = 1;
            }
            s_flag = excl;
        }
        __syncthreads();
        if (s_flag) return;
        worker_loop(x, Wq, Wk, Wv, Wg, Wo, post_g, post_b, C, U.wk.As, U.wk.Bs, s_tile);
        return;
    }

    ScanSmem& SC = U.sc;
    const int h = blockIdx.x;
    const int l = tid & 31;
    const int hb = h * 64;

    if (tid == 0) {
        g_smids[h] = (int)my_smid();
        __threadfence();
        atomicAdd(&g_nscan, 1);
    }

    if (tid < 128) {
        // ================= GROUP A =================
        const int aw   = tid >> 5;
        const int ecol = tid & 63;
        const int rgrp = tid >> 6;
        const int lb   = tid >> 6;
        const int le   = tid & 63;

        float Wreg[32];
#pragma unroll
        for (int j = 0; j < 32; j++)
            Wreg[j] = fw_W[h * 4096 + (rgrp * 32 + j) * 64 + ecol];

        float bias0 = fw_b[hb + l],  bias1 = fw_b[hb + l + 32];
        float g0    = fw_g[hb + l],  g1    = fw_g[hb + l + 32];
        float bl0   = fw_bl[hb + l], bl1   = fw_bl[hb + l + 32];

        wait_cnt(&g_ready[0], 192);
        // token 0: load + store into ks[0]/ts[0]
        {
            size_t b0 = (size_t)lb * E_ + hb + le;
            float k0 = g_k[b0],          k1 = g_k[b0 + 2 * E_];
            float v0 = g_v[b0],          v1 = g_v[b0 + 2 * E_];
            SC.ks[0][lb][le]     = k0;   SC.ks[0][lb + 2][le] = k1;
            SC.ts[0][lb][le]     = v0 - k0;
            SC.ts[0][lb + 2][le] = v1 - k1;
        }
        // token 1 into regs
        float kf0, kf1, vf0, vf1;
        {
            size_t b1 = (size_t)(B_ + lb) * E_ + hb + le;
            kf0 = g_k[b1]; kf1 = g_k[b1 + 2 * E_];
            vf0 = g_v[b1]; vf1 = g_v[b1 + 2 * E_];
        }
        BAR_A();   // ks[0]/ts[0] visible to matvec

        for (int s = 0; s < S_; s++) {
            const int par = s & 1;

            const float4* k40 = (const float4*)&SC.ks[par][0][rgrp * 32];
            const float4* k41 = (const float4*)&SC.ks[par][1][rgrp * 32];
            const float4* k42 = (const float4*)&SC.ks[par][2][rgrp * 32];
            const float4* k43 = (const float4*)&SC.ks[par][3][rgrp * 32];
            float a0 = 0.f, a1 = 0.f, a2 = 0.f, a3 = 0.f;
#pragma unroll
            for (int i = 0; i < 8; i++) {
                float4 c0 = k40[i], c1 = k41[i], c2 = k42[i], c3 = k43[i];
                float w0 = Wreg[4*i], w1 = Wreg[4*i+1], w2 = Wreg[4*i+2], w3 = Wreg[4*i+3];
                a0 += c0.x*w0 + c0.y*w1 + c0.z*w2 + c0.w*w3;
                a1 += c1.x*w0 + c1.y*w1 + c1.z*w2 + c1.w*w3;
                a2 += c2.x*w0 + c2.y*w1 + c2.z*w2 + c2.w*w3;
                a3 += c3.x*w0 + c3.y*w1 + c3.z*w2 + c3.w*w3;
            }
            SC.pt[rgrp][0][ecol] = a0;
            SC.pt[rgrp][1][ecol] = a1;
            SC.pt[rgrp][2][ecol] = a2;
            SC.pt[rgrp][3][ecol] = a3;
            BAR_A();   // pt ready; also orders last token's ks reads vs store below

            // store token s+1 (regs) into the other parity buffer
            if (s + 1 < S_) {
                const int np = par ^ 1;
                SC.ks[np][lb][le]     = kf0;
                SC.ks[np][lb + 2][le] = kf1;
                SC.ts[np][lb][le]     = vf0 - kf0;
                SC.ts[np][lb + 2][le] = vf1 - kf1;
                if (s + 2 < S_) {
                    if (((s + 2) & 127) == 0)
                        wait_cnt(&g_ready[(s + 2) >> 7], ready_tgt((s + 2) >> 7));
                    size_t nb = (size_t)((s + 2) * B_ + lb) * E_ + hb + le;
                    kf0 = g_k[nb]; kf1 = g_k[nb + 2 * E_];
                    vf0 = g_v[nb]; vf1 = g_v[nb + 2 * E_];
                }
            }

            float z0 = bias0 + SC.pt[0][aw][l]      + SC.pt[1][aw][l];
            float z1 = bias1 + SC.pt[0][aw][l + 32] + SC.pt[1][aw][l + 32];
            float sum = z0 + z1, sq = z0 * z0 + z1 * z1;
            bfly2(sum, sq);
            float mu   = sum * INV64;
            float rstd = rsqrtf(sq * INV64 - mu * mu + LN_EPS);
            float xh0 = (z0 - mu) * rstd, xh1 = (z1 - mu) * rstd;

            float t0 = SC.ts[par][aw][l], t1 = SC.ts[par][aw][l + 32];
            float p0 = xh0 * g0 + bl0, p1 = xh1 * g1 + bl1;
            float dp0 = C_GRAD * (p0 - t0), dp1 = C_GRAD * (p1 - t1);
            float dx0 = dp0 * g0, dx1 = dp1 * g1;
            float S1 = dx0 + dx1, S2 = dx0 * xh0 + dx1 * xh1;
            bfly2(S1, S2);
            float dh0 = rstd * (dx0 - (S1 + xh0 * S2) * INV64);
            float dh1 = rstd * (dx1 - (S1 + xh1 * S2) * INV64);
            SC.d1h[aw][l]          = dh0;
            SC.d1h[aw][l + 32]     = dh1;
            SC.d1x[par][aw][l]      = dp0 * xh0;
            SC.d1x[par][aw][l + 32] = dp1 * xh1;
            SC.d1p[par][aw][l]      = dp0;
            SC.d1p[par][aw][l + 32] = dp1;
            BAR_FULL();                                   // A3

            float sx0 = SC.d1x[par][0][l] + SC.d1x[par][1][l] + SC.d1x[par][2][l] + SC.d1x[par][3][l];
            float sx1 = SC.d1x[par][0][l+32] + SC.d1x[par][1][l+32] + SC.d1x[par][2][l+32] + SC.d1x[par][3][l+32];
            float sp0 = SC.d1p[par][0][l] + SC.d1p[par][1][l] + SC.d1p[par][2][l] + SC.d1p[par][3][l];
            float sp1 = SC.d1p[par][0][l+32] + SC.d1p[par][1][l+32] + SC.d1p[par][2][l+32] + SC.d1p[par][3][l+32];
            g0 -= LR * sx0; g1 -= LR * sx1;
            bl0 -= LR * sp0; bl1 -= LR * sp1;

            float m0 = SC.Ms[aw][0], m1 = SC.Ms[aw][1], m2 = SC.Ms[aw][2], m3 = SC.Ms[aw][3];
            z0 += m0 * SC.d1h[0][l] + m1 * SC.d1h[1][l] + m2 * SC.d1h[2][l] + m3 * SC.d1h[3][l];
            z1 += m0 * SC.d1h[0][l+32] + m1 * SC.d1h[1][l+32] + m2 * SC.d1h[2][l+32] + m3 * SC.d1h[3][l+32];

            sum = z0 + z1; sq = z0 * z0 + z1 * z1;
            bfly2(sum, sq);
            mu   = sum * INV64;
            rstd = rsqrtf(sq * INV64 - mu * mu + LN_EPS);
            xh0 = (z0 - mu) * rstd; xh1 = (z1 - mu) * rstd;

            p0 = xh0 * g0 + bl0; p1 = xh1 * g1 + bl1;
            dp0 = C_GRAD * (p0 - t0); dp1 = C_GRAD * (p1 - t1);
            dx0 = dp0 * g0; dx1 = dp1 * g1;
            S1 = dx0 + dx1; S2 = dx0 * xh0 + dx1 * xh1;
            bfly2(S1, S2);
            float e0 = rstd * (dx0 - (S1 + xh0 * S2) * INV64);
            float e1 = rstd * (dx1 - (S1 + xh1 * S2) * INV64);

            SC.z2s[aw][l]       = z0;   SC.z2s[aw][l + 32]  = z1;
            SC.d2h[aw][l]       = e0;   SC.d2h[aw][l + 32]  = e1;
            SC.d2x[aw][l]       = dp0 * xh0; SC.d2x[aw][l + 32] = dp1 * xh1;
            SC.d2p[aw][l]       = dp0;  SC.d2p[aw][l + 32]  = dp1;
            SC.dsum[aw][l]      = dh0 + e0;
            SC.dsum[aw][l + 32] = dh1 + e1;
            BAR_FULL();                                   // S3

            sx0 = SC.d2x[0][l] + SC.d2x[1][l] + SC.d2x[2][l] + SC.d2x[3][l];
            sx1 = SC.d2x[0][l+32] + SC.d2x[1][l+32] + SC.d2x[2][l+32] + SC.d2x[3][l+32];
            sp0 = SC.d2p[0][l] + SC.d2p[1][l] + SC.d2p[2][l] + SC.d2p[3][l];
            sp1 = SC.d2p[0][l+32] + SC.d2p[1][l+32] + SC.d2p[2][l+32] + SC.d2p[3][l+32];
            g0 -= LR * sx0; g1 -= LR * sx1;
            bl0 -= LR * sp0; bl1 -= LR * sp1;
            bias0 -= LR * (SC.dsum[0][l] + SC.dsum[1][l] + SC.dsum[2][l] + SC.dsum[3][l]);
            bias1 -= LR * (SC.dsum[0][l+32] + SC.dsum[1][l+32] + SC.dsum[2][l+32] + SC.dsum[3][l+32]);

            float ds0 = LR * SC.dsum[0][ecol];
            float ds1 = LR * SC.dsum[1][ecol];
            float ds2 = LR * SC.dsum[2][ecol];
            float ds3 = LR * SC.dsum[3][ecol];
#pragma unroll
            for (int i = 0; i < 8; i++) {
                float4 c0 = k40[i], c1 = k41[i], c2 = k42[i], c3 = k43[i];
                Wreg[4*i]   -= c0.x*ds0 + c1.x*ds1 + c2.x*ds2 + c3.x*ds3;
                Wreg[4*i+1] -= c0.y*ds0 + c1.y*ds1 + c2.y*ds2 + c3.y*ds3;
                Wreg[4*i+2] -= c0.z*ds0 + c1.z*ds1 + c2.z*ds2 + c3.z*ds3;
                Wreg[4*i+3] -= c0.w*ds0 + c1.w*ds1 + c2.w*ds2 + c3.w*ds3;
            }
        }
    } else {
        // ================= GROUP B =================
        const int bw = (tid >> 5) - 4;

        float g0  = fw_g[hb + l],  g1  = fw_g[hb + l + 32];
        float bl0 = fw_bl[hb + l], bl1 = fw_bl[hb + l + 32];
        float tg0 = ttt_g[hb + l], tg1 = ttt_g[hb + l + 32];
        float tb0 = ttt_b[hb + l], tb1 = ttt_b[hb + l + 32];

        wait_cnt(&g_ready[0], 192);
        float kk0[4], kk1[4];
#pragma unroll
        for (int b = 0; b < 4; b++) {
            kk0[b] = g_k[(size_t)b * E_ + hb + l];
            kk1[b] = g_k[(size_t)b * E_ + hb + l + 32];
        }
        float Mreg[4];
        {
            float P0 = kk0[bw]*kk0[0] + kk1[bw]*kk1[0];
            float P1 = kk0[bw]*kk0[1] + kk1[bw]*kk1[1];
            float P2 = kk0[bw]*kk0[2] + kk1[bw]*kk1[2];
            float P3 = kk0[bw]*kk0[3] + kk1[bw]*kk1[3];
            bfly4(P0, P1, P2, P3);
            Mreg[0] = -LR * (P0 + 1.0f);
            Mreg[1] = -LR * (P1 + 1.0f);
            Mreg[2] = -LR * (P2 + 1.0f);
            Mreg[3] = -LR * (P3 + 1.0f);
            if (l == 0) {
                SC.Ms[bw][0] = Mreg[0]; SC.Ms[bw][1] = Mreg[1];
                SC.Ms[bw][2] = Mreg[2]; SC.Ms[bw][3] = Mreg[3];
            }
        }
        float q0 = g_q[(size_t)bw * E_ + hb + l];
        float q1 = g_q[(size_t)bw * E_ + hb + l + 32];
#pragma unroll
        for (int b = 0; b < 4; b++) {
            kk0[b] = g_k[(size_t)(1 * B_ + b) * E_ + hb + l];
            kk1[b] = g_k[(size_t)(1 * B_ + b) * E_ + hb + l + 32];
        }

        for (int s = 0; s < S_; s++) {
            BAR_FULL();                                   // A3
            BAR_FULL();                                   // S3
            const int par = s & 1;

            float sx0 = 0.f, sx1 = 0.f, sp0 = 0.f, sp1 = 0.f;
#pragma unroll
            for (int b = 0; b < 4; b++) {
                sx0 += SC.d1x[par][b][l]      + SC.d2x[b][l];
                sx1 += SC.d1x[par][b][l + 32] + SC.d2x[b][l + 32];
                sp0 += SC.d1p[par][b][l]      + SC.d2p[b][l];
                sp1 += SC.d1p[par][b][l + 32] + SC.d2p[b][l + 32];
            }
            g0 -= LR * sx0; g1 -= LR * sx1;
            bl0 -= LR * sp0; bl1 -= LR * sp1;

            float z0 = SC.z2s[bw][l]
                     + Mreg[0]*SC.d2h[0][l] + Mreg[1]*SC.d2h[1][l]
                     + Mreg[2]*SC.d2h[2][l] + Mreg[3]*SC.d2h[3][l];
            float z1 = SC.z2s[bw][l + 32]
                     + Mreg[0]*SC.d2h[0][l+32] + Mreg[1]*SC.d2h[1][l+32]
                     + Mreg[2]*SC.d2h[2][l+32] + Mreg[3]*SC.d2h[3][l+32];

            float sum = z0 + z1, sq = z0 * z0 + z1 * z1;
            bfly2(sum, sq);
            float mu = sum * INV64;
            float rs = rsqrtf(sq * INV64 - mu * mu + LN_EPS);
            float p0 = (z0 - mu) * rs * g0 + bl0;
            float p1 = (z1 - mu) * rs * g1 + bl1;

            sum = p0 + p1; sq = p0 * p0 + p1 * p1;
            bfly2(sum, sq);
            mu = sum * INV64;
            rs = rsqrtf(sq * INV64 - mu * mu + LN_EPS);
            size_t ob = (size_t)(s * B_ + bw) * E_ + hb + l;
            g_scan[ob]      = q0 + (p0 - mu) * rs * tg0 + tb0;
            g_scan[ob + 32] = q1 + (p1 - mu) * rs * tg1 + tb1;

            if ((s & 127) == 127) {
                __threadfence();
                BAR_B();
                if (tid == 128) atomicAdd(&g_scan_done[s >> 7], 1);
            }

            if (s + 1 < S_) {
                float P0 = kk0[bw]*kk0[0] + kk1[bw]*kk1[0];
                float P1 = kk0[bw]*kk0[1] + kk1[bw]*kk1[1];
                float P2 = kk0[bw]*kk0[2] + kk1[bw]*kk1[2];
                float P3 = kk0[bw]*kk0[3] + kk1[bw]*kk1[3];
                bfly4(P0, P1, P2, P3);
                Mreg[0] = -LR * (P0 + 1.0f);
                Mreg[1] = -LR * (P1 + 1.0f);
                Mreg[2] = -LR * (P2 + 1.0f);
                Mreg[3] = -LR * (P3 + 1.0f);
                if (l == 0) {
                    SC.Ms[bw][0] = Mreg[0]; SC.Ms[bw][1] = Mreg[1];
                    SC.Ms[bw][2] = Mreg[2]; SC.Ms[bw][3] = Mreg[3];
                }
                size_t qb = (size_t)((s + 1) * B_ + bw) * E_ + hb + l;
                q0 = g_q[qb];
                q1 = g_q[qb + 32];
                if (s + 2 < S_) {
                    if (((s + 2) & 127) == 0)
                        wait_cnt(&g_ready[(s + 2) >> 7], ready_tgt((s + 2) >> 7));
#pragma unroll
                    for (int b = 0; b < 4; b++) {
                        size_t kb = (size_t)((s + 2) * B_ + b) * E_ + hb + l;
                        kk0[b] = g_k[kb];
                        kk1[b] = g_k[kb + 32];
                    }
                }
            }
        }
    }

    worker_loop(x, Wq, Wk, Wv, Wg, Wo, post_g, post_b, C, U.wk.As, U.wk.Bs, s_tile);
}

__global__ void reset_kernel()
{
    const int t = threadIdx.x;
    if (t < 16) { g_ready[t] = 0; g_gate_ready[t] = 0; g_scan_done[t] = 0; }
    if (t < 64) g_post_done[t] = 0;
    if (t == 64) { g_tile = 0; g_nscan = 0; }
}

extern "C" void kernel_launch(void* const* d_in, const int* in_sizes, int n_in,
                              void* d_out, int out_size)
{
    const float* x      = (const float*)d_in[0];
    const float* Wq     = (const float*)d_in[1];
    const float* Wk     = (const float*)d_in[2];
    const float* Wv     = (const float*)d_in[3];
    const float* Wo     = (const float*)d_in[4];
    const float* Wg     = (const float*)d_in[5];
    const float* fw_W   = (const float*)d_in[6];
    const float* fw_b   = (const float*)d_in[7];
    const float* fw_g   = (const float*)d_in[8];
    const float* fw_bl  = (const float*)d_in[9];
    const float* ttt_g  = (const float*)d_in[10];
    const float* ttt_b  = (const float*)d_in[11];
    const float* post_g = (const float*)d_in[12];
    const float* post_b = (const float*)d_in[13];

    fused_kernel<<<16 + N_WORKERS, 256>>>(x, Wq, Wk, Wv, Wg, Wo,
                                          fw_W, fw_b, fw_g, fw_bl,
                                          ttt_g, ttt_b, post_g, post_b,
                                          (float*)d_out);
    reset_kernel<<<1, 128>>>();
}

// round 15
// speedup vs baseline: 1.0452x; 1.0452x over previous
#include <cuda_runtime.h>
#include <cstdint>

#define B_ 4
#define S_ 2048
#define E_ 1024
#define H_ 16
#define D_ 64
#define LN_EPS 1e-5f
#define LR 0.1f
#define INV64 0.015625f
#define C_GRAD (2.0f / 4096.0f)

#define N_WORKERS 296
#define NT_HALF 576
#define NT_QKV  1824
#define NT_G1   2336
#define NT_POST 2400
#define NT_ALL  2912

typedef unsigned long long ull;

__device__ float g_q[S_ * B_ * E_];
__device__ float g_k[S_ * B_ * E_];
__device__ float g_v[S_ * B_ * E_];
__device__ float g_gate[B_ * S_ * E_];
__device__ float g_scan[S_ * B_ * E_];
__device__ float g_y[B_ * S_ * E_];
__device__ int   g_ready[16];
__device__ int   g_gate_ready[16];
__device__ int   g_scan_done[16];
__device__ int   g_post_done[64];
__device__ int   g_tile;
__device__ int   g_nscan;
__device__ int   g_smids[16];

__device__ __forceinline__ int ready_tgt(int c) { return (c < 3) ? 192 : 96; }

struct __align__(16) ScanSmem {
    float ks[2][B_][D_], ts[2][B_][D_], pt[2][B_][D_];
    float d1h[B_][D_], d1x[2][B_][D_], d1p[2][B_][D_];
    float d2h[B_][D_], d2x[B_][D_], d2p[B_][D_];
    float z2s[B_][D_], dsum[B_][D_];
    float Ms[B_][B_];
};
struct __align__(16) WorkSmem { float As[2][8][128]; float Bs[2][8][128]; };
union SmemU { ScanSmem sc; WorkSmem wk; };

__device__ __forceinline__ void bfly2(float& a, float& b)
{
#pragma unroll
    for (int o = 16; o > 0; o >>= 1) {
        a += __shfl_xor_sync(0xffffffffu, a, o);
        b += __shfl_xor_sync(0xffffffffu, b, o);
    }
}
__device__ __forceinline__ void bfly4(float& a, float& b, float& c, float& d)
{
#pragma unroll
    for (int o = 16; o > 0; o >>= 1) {
        a += __shfl_xor_sync(0xffffffffu, a, o);
        b += __shfl_xor_sync(0xffffffffu, b, o);
        c += __shfl_xor_sync(0xffffffffu, c, o);
        d += __shfl_xor_sync(0xffffffffu, d, o);
    }
}
// 7 interleaved reduction chains: one 5-level ladder, chains pipeline.
__device__ __forceinline__ void bfly7(float& a, float& b, float& c, float& d,
                                      float& e, float& f, float& g)
{
#pragma unroll
    for (int o = 16; o > 0; o >>= 1) {
        a += __shfl_xor_sync(0xffffffffu, a, o);
        b += __shfl_xor_sync(0xffffffffu, b, o);
        c += __shfl_xor_sync(0xffffffffu, c, o);
        d += __shfl_xor_sync(0xffffffffu, d, o);
        e += __shfl_xor_sync(0xffffffffu, e, o);
        f += __shfl_xor_sync(0xffffffffu, f, o);
        g += __shfl_xor_sync(0xffffffffu, g, o);
    }
}
__device__ __forceinline__ void wait_cnt(int* p, int target)
{
    if (*(volatile int*)p < target) {
        while (*(volatile int*)p < target) __nanosleep(256);
    }
    __threadfence();
}
__device__ __forceinline__ unsigned my_smid()
{
    unsigned s; asm("mov.u32 %0, %%smid;" : "=r"(s)); return s;
}
__device__ __forceinline__ float gelu_t(float x)
{
    float t = 0.7978845608028654f * (x + 0.044715f * x * x * x);
    return 0.5f * x * (1.0f + tanhf(t));
}

#define BAR_A()    asm volatile("bar.sync 1, 128;" ::: "memory")
#define BAR_B()    asm volatile("bar.sync 2, 128;" ::: "memory")
#define BAR_FULL() asm volatile("bar.sync 0, 256;" ::: "memory")

// ---------------------------------------------------------------------------
__device__ void worker_loop(const float* __restrict__ x,
                            const float* __restrict__ Wq, const float* __restrict__ Wk,
                            const float* __restrict__ Wv, const float* __restrict__ Wg,
                            const float* __restrict__ Wo,
                            const float* __restrict__ post_g, const float* __restrict__ post_b,
                            float* __restrict__ C,
                            float (&As)[2][8][128], float (&Bs)[2][8][128],
                            int& s_tile)
{
    const int tid = threadIdx.x;
    const int lm = tid >> 1, lk = (tid & 1) * 4;
    const int tm = (tid >> 4) * 8, tn = (tid & 15) * 8;
    const int warp = tid >> 5, lane = tid & 31;

    for (;;) {
        if (tid == 0) s_tile = atomicAdd(&g_tile, 1);
        __syncthreads();
        const int gid = s_tile;
        if (gid >= NT_ALL) break;

        if (gid < NT_HALF) {
            // ======= half qkv tile (chunks 0-2, N-split: 128 x 64) =======
            const int t2 = gid >> 1, nh = gid & 1;
            const int bmp = t2 / 24, bn2 = t2 % 24;
            const int chunk = bmp >> 2, b = bmp & 3;
            const int m0 = b * 2048 + chunk * 128;
            const int nbase = bn2 * 128;
            const int p2 = nbase >> 10;
            const float* Bmat = (p2 == 0) ? Wq : (p2 == 1) ? Wk : Wv;
            const int frow = (nbase & 1023) + nh * 64;
            const float* ArowH = x + (size_t)(m0 + lm) * 1024 + lk;
            const float* BrowH = Bmat + (size_t)(frow + lm) * 1024 + lk;
            const int tmH = (tid >> 3) * 4;
            const int tnH = (tid & 7) * 8;

            ull acc[4][4];
#pragma unroll
            for (int i = 0; i < 4; i++)
#pragma unroll
                for (int j = 0; j < 4; j++) acc[i][j] = 0ull;

            {
                float4 a4 = *(const float4*)(ArowH);
                As[0][lk+0][lm] = a4.x; As[0][lk+1][lm] = a4.y;
                As[0][lk+2][lm] = a4.z; As[0][lk+3][lm] = a4.w;
                if (tid < 128) {
                    float4 b4 = *(const float4*)(BrowH);
                    Bs[0][lk+0][lm] = b4.x; Bs[0][lk+1][lm] = b4.y;
                    Bs[0][lk+2][lm] = b4.z; Bs[0][lk+3][lm] = b4.w;
                }
            }
            __syncthreads();

            for (int t = 0; t < 128; t++) {
                const int cur = t & 1, nxt = cur ^ 1;
                float4 a4, b4;
                const bool more = (t + 1 < 128);
                if (more) {
                    a4 = *(const float4*)(ArowH + (t + 1) * 8);
                    if (tid < 128) b4 = *(const float4*)(BrowH + (t + 1) * 8);
                }
#pragma unroll
                for (int kk = 0; kk < 8; kk++) {
                    ull b2[4];
#pragma unroll
                    for (int j = 0; j < 4; j++)
                        b2[j] = *(const ull*)&Bs[cur][kk][tnH + 2*j];
                    float4 av = *(const float4*)&As[cur][kk][tmH];
                    ull ax0, ax1, ax2, ax3;
                    asm("mov.b64 %0, {%1, %1};" : "=l"(ax0) : "f"(av.x));
                    asm("mov.b64 %0, {%1, %1};" : "=l"(ax1) : "f"(av.y));
                    asm("mov.b64 %0, {%1, %1};" : "=l"(ax2) : "f"(av.z));
                    asm("mov.b64 %0, {%1, %1};" : "=l"(ax3) : "f"(av.w));
#pragma unroll
                    for (int j = 0; j < 4; j++) {
                        asm("fma.rn.f32x2 %0, %1, %2, %0;" : "+l"(acc[0][j]) : "l"(ax0), "l"(b2[j]));
                        asm("fma.rn.f32x2 %0, %1, %2, %0;" : "+l"(acc[1][j]) : "l"(ax1), "l"(b2[j]));
                        asm("fma.rn.f32x2 %0, %1, %2, %0;" : "+l"(acc[2][j]) : "l"(ax2), "l"(b2[j]));
                        asm("fma.rn.f32x2 %0, %1, %2, %0;" : "+l"(acc[3][j]) : "l"(ax3), "l"(b2[j]));
                    }
                }
                if (more) {
                    As[nxt][lk+0][lm] = a4.x; As[nxt][lk+1][lm] = a4.y;
                    As[nxt][lk+2][lm] = a4.z; As[nxt][lk+3][lm] = a4.w;
                    if (tid < 128) {
                        Bs[nxt][lk+0][lm] = b4.x; Bs[nxt][lk+1][lm] = b4.y;
                        Bs[nxt][lk+2][lm] = b4.z; Bs[nxt][lk+3][lm] = b4.w;
                    }
                }
                __syncthreads();
            }

            const int f = frow + tnH;
#pragma unroll
            for (int i = 0; i < 4; i++) {
                int s = chunk * 128 + tmH + i;
                float* dstf = (p2 == 0 ? g_q : p2 == 1 ? g_k : g_v)
                              + (size_t)(s * B_ + b) * 1024 + f;
                ull* dst = (ull*)dstf;
#pragma unroll
                for (int j = 0; j < 4; j++) dst[j] = acc[i][j];
            }
            __threadfence();
            __syncthreads();
            if (tid == 0) atomicAdd(&g_ready[chunk], 1);
            continue;
        }

        if (gid >= NT_G1 && gid < NT_POST) {
            // ---------------- post tile ----------------
            const int t = gid - NT_G1;
            const int chunk = t >> 2, b = t & 3;
            wait_cnt(&g_scan_done[chunk], 16);
            wait_cnt(&g_gate_ready[chunk], 32);
            for (int r = warp; r < 128; r += 8) {
                const int s = chunk * 128 + r;
                const float4* in = (const float4*)(g_scan + (size_t)(s * B_ + b) * E_);
                const float4* gp = (const float4*)(g_gate + (size_t)(b * 2048 + s) * E_);
                float4* out = (float4*)(g_y + (size_t)(b * 2048 + s) * E_);
                float4 v[8]; float sum = 0.f, sq = 0.f;
#pragma unroll
                for (int i = 0; i < 8; i++) {
                    v[i] = in[lane + 32 * i];
                    sum += v[i].x + v[i].y + v[i].z + v[i].w;
                    sq  += v[i].x*v[i].x + v[i].y*v[i].y + v[i].z*v[i].z + v[i].w*v[i].w;
                }
                bfly2(sum, sq);
                float mu = sum * (1.0f / 1024.0f);
                float rs = rsqrtf(sq * (1.0f / 1024.0f) - mu * mu + LN_EPS);
#pragma unroll
                for (int i = 0; i < 8; i++) {
                    float4 pg = ((const float4*)post_g)[lane + 32 * i];
                    float4 pb = ((const float4*)post_b)[lane + 32 * i];
                    float4 gg = gp[lane + 32 * i];
                    float4 o;
                    o.x = gelu_t(gg.x) * ((v[i].x - mu) * rs * pg.x + pb.x);
                    o.y = gelu_t(gg.y) * ((v[i].y - mu) * rs * pg.y + pb.y);
                    o.z = gelu_t(gg.z) * ((v[i].z - mu) * rs * pg.z + pb.z);
                    o.w = gelu_t(gg.w) * ((v[i].w - mu) * rs * pg.w + pb.w);
                    out[lane + 32 * i] = o;
                }
            }
            __threadfence();
            __syncthreads();
            if (tid == 0) atomicAdd(&g_post_done[chunk * 4 + b], 1);
            continue;
        }

        // ---------------- full gemm tile (128x128) ----------------
        const float *Arow, *Brow;
        int chunk, b, bn, p, m0;
        if (gid < NT_QKV) {
            int t = gid - 288;
            int bmp = t / 24; bn = t % 24;
            chunk = bmp >> 2; b = bmp & 3;
            m0 = b * 2048 + chunk * 128;
            const int nbase = bn * 128;
            p = nbase >> 10;
            const float* Bmat = (p == 0) ? Wq : (p == 1) ? Wk : Wv;
            Arow = x + (size_t)(m0 + lm) * 1024 + lk;
            Brow = Bmat + (size_t)((nbase & 1023) + lm) * 1024 + lk;
        } else if (gid < NT_G1) {
            int g2 = gid - NT_QKV;
            int bmp = g2 >> 3; bn = 24 + (g2 & 7);
            chunk = bmp >> 2; b = bmp & 3;
            m0 = b * 2048 + chunk * 128;
            p = 3;
            Arow = x + (size_t)(m0 + lm) * 1024 + lk;
            Brow = Wg + (size_t)(((bn * 128) & 1023) + lm) * 1024 + lk;
        } else {
            int g2 = gid - NT_POST;
            chunk = g2 >> 5;
            int rr = g2 & 31;
            b = rr >> 3; bn = rr & 7;
            p = 4;
            m0 = b * 2048 + chunk * 128;
            wait_cnt(&g_post_done[chunk * 4 + b], 1);
            Arow = g_y + (size_t)(m0 + lm) * 1024 + lk;
            Brow = Wo + (size_t)(bn * 128 + lm) * 1024 + lk;
        }

        ull acc[8][4];
#pragma unroll
        for (int i = 0; i < 8; i++)
#pragma unroll
            for (int j = 0; j < 4; j++) acc[i][j] = 0ull;

        {
            float4 a4 = *(const float4*)(Arow);
            float4 b4 = *(const float4*)(Brow);
            As[0][lk+0][lm] = a4.x; As[0][lk+1][lm] = a4.y;
            As[0][lk+2][lm] = a4.z; As[0][lk+3][lm] = a4.w;
            Bs[0][lk+0][lm] = b4.x; Bs[0][lk+1][lm] = b4.y;
            Bs[0][lk+2][lm] = b4.z; Bs[0][lk+3][lm] = b4.w;
        }
        __syncthreads();

        for (int t = 0; t < 128; t++) {
            const int cur = t & 1, nxt = cur ^ 1;
            float4 a4, b4;
            const bool more = (t + 1 < 128);
            if (more) {
                a4 = *(const float4*)(Arow + (t + 1) * 8);
                b4 = *(const float4*)(Brow + (t + 1) * 8);
            }
#pragma unroll
            for (int kk = 0; kk < 8; kk++) {
                ull b2[4];
#pragma unroll
                for (int j = 0; j < 4; j++)
                    b2[j] = *(const ull*)&Bs[cur][kk][tn + 2*j];
                float2 a2[4];
#pragma unroll
                for (int i = 0; i < 4; i++)
                    a2[i] = *(const float2*)&As[cur][kk][tm + 2*i];
#pragma unroll
                for (int i = 0; i < 4; i++) {
                    ull axlo, axhi;
                    asm("mov.b64 %0, {%1, %1};" : "=l"(axlo) : "f"(a2[i].x));
                    asm("mov.b64 %0, {%1, %1};" : "=l"(axhi) : "f"(a2[i].y));
#pragma unroll
                    for (int j = 0; j < 4; j++) {
                        asm("fma.rn.f32x2 %0, %1, %2, %0;"
                            : "+l"(acc[2*i][j]) : "l"(axlo), "l"(b2[j]));
                        asm("fma.rn.f32x2 %0, %1, %2, %0;"
                            : "+l"(acc[2*i+1][j]) : "l"(axhi), "l"(b2[j]));
                    }
                }
            }
            if (more) {
                As[nxt][lk+0][lm] = a4.x; As[nxt][lk+1][lm] = a4.y;
                As[nxt][lk+2][lm] = a4.z; As[nxt][lk+3][lm] = a4.w;
                Bs[nxt][lk+0][lm] = b4.x; Bs[nxt][lk+1][lm] = b4.y;
                Bs[nxt][lk+2][lm] = b4.z; Bs[nxt][lk+3][lm] = b4.w;
            }
            __syncthreads();
        }

        if (p == 4) {
#pragma unroll
            for (int i = 0; i < 8; i++) {
                int m = m0 + tm + i;
                ull* crow = (ull*)(C + (size_t)m * 1024 + bn * 128 + tn);
#pragma unroll
                for (int j = 0; j < 4; j++) crow[j] = acc[i][j];
            }
            __syncthreads();
        } else {
            const int f = ((bn * 128) & 1023) + tn;
#pragma unroll
            for (int i = 0; i < 8; i++) {
                int s = chunk * 128 + tm + i;
                float* dstf = (p == 3)
                    ? g_gate + (size_t)(b * 2048 + s) * 1024 + f
                    : (p == 0 ? g_q : p == 1 ? g_k : g_v) + (size_t)(s * B_ + b) * 1024 + f;
                ull* dst = (ull*)dstf;
#pragma unroll
                for (int j = 0; j < 4; j++) dst[j] = acc[i][j];
            }
            __threadfence();
            __syncthreads();
            if (tid == 0) {
                if (p < 3) atomicAdd(&g_ready[chunk], 1);
                else       atomicAdd(&g_gate_ready[chunk], 1);
            }
        }
    }
}

// ---------------------------------------------------------------------------
// Fused: blocks 0-15 = TTT scan (fused LN+bwd reductions); blocks 16+ workers.
// ---------------------------------------------------------------------------
__global__ void __launch_bounds__(256, 2)
fused_kernel(const float* __restrict__ x,
             const float* __restrict__ Wq, const float* __restrict__ Wk,
             const float* __restrict__ Wv, const float* __restrict__ Wg,
             const float* __restrict__ Wo,
             const float* __restrict__ fw_W, const float* __restrict__ fw_b,
             const float* __restrict__ fw_g, const float* __restrict__ fw_bl,
             const float* __restrict__ ttt_g, const float* __restrict__ ttt_b,
             const float* __restrict__ post_g, const float* __restrict__ post_b,
             float* __restrict__ C)
{
    __shared__ SmemU U;
    __shared__ int s_flag, s_tile;
    const int tid = threadIdx.x;

    if (blockIdx.x >= 16) {
        if (tid == 0) {
            unsigned smid = my_smid();
            int it = 0;
            while (*(volatile int*)&g_nscan < 16 && it < 50000) { __nanosleep(128); it++; }
            __threadfence();
            int excl = 0;
            if (*(volatile int*)&g_nscan >= 16) {
#pragma unroll
                for (int i = 0; i < 16; i++)
                    if (g_smids[i] == (int)smid) excl = 1;
            }
            s_flag = excl;
        }
        __syncthreads();
        if (s_flag) return;
        worker_loop(x, Wq, Wk, Wv, Wg, Wo, post_g, post_b, C, U.wk.As, U.wk.Bs, s_tile);
        return;
    }

    ScanSmem& SC = U.sc;
    const int h = blockIdx.x;
    const int l = tid & 31;
    const int hb = h * 64;

    if (tid == 0) {
        g_smids[h] = (int)my_smid();
        __threadfence();
        atomicAdd(&g_nscan, 1);
    }

    if (tid < 128) {
        // ================= GROUP A =================
        const int aw   = tid >> 5;
        const int ecol = tid & 63;
        const int rgrp = tid >> 6;
        const int lb   = tid >> 6;
        const int le   = tid & 63;

        float Wreg[32];
#pragma unroll
        for (int j = 0; j < 32; j++)
            Wreg[j] = fw_W[h * 4096 + (rgrp * 32 + j) * 64 + ecol];

        float bias0 = fw_b[hb + l],  bias1 = fw_b[hb + l + 32];
        float g0    = fw_g[hb + l],  g1    = fw_g[hb + l + 32];
        float bl0   = fw_bl[hb + l], bl1   = fw_bl[hb + l + 32];

        wait_cnt(&g_ready[0], 192);
        {
            size_t b0 = (size_t)lb * E_ + hb + le;
            float k0 = g_k[b0],          k1 = g_k[b0 + 2 * E_];
            float v0 = g_v[b0],          v1 = g_v[b0 + 2 * E_];
            SC.ks[0][lb][le]     = k0;   SC.ks[0][lb + 2][le] = k1;
            SC.ts[0][lb][le]     = v0 - k0;
            SC.ts[0][lb + 2][le] = v1 - k1;
        }
        float kf0, kf1, vf0, vf1;
        {
            size_t b1 = (size_t)(B_ + lb) * E_ + hb + le;
            kf0 = g_k[b1]; kf1 = g_k[b1 + 2 * E_];
            vf0 = g_v[b1]; vf1 = g_v[b1 + 2 * E_];
        }
        BAR_A();

        for (int s = 0; s < S_; s++) {
            const int par = s & 1;

            const float4* k40 = (const float4*)&SC.ks[par][0][rgrp * 32];
            const float4* k41 = (const float4*)&SC.ks[par][1][rgrp * 32];
            const float4* k42 = (const float4*)&SC.ks[par][2][rgrp * 32];
            const float4* k43 = (const float4*)&SC.ks[par][3][rgrp * 32];
            float a0 = 0.f, a1 = 0.f, a2 = 0.f, a3 = 0.f;
#pragma unroll
            for (int i = 0; i < 8; i++) {
                float4 c0 = k40[i], c1 = k41[i], c2 = k42[i], c3 = k43[i];
                float w0 = Wreg[4*i], w1 = Wreg[4*i+1], w2 = Wreg[4*i+2], w3 = Wreg[4*i+3];
                a0 += c0.x*w0 + c0.y*w1 + c0.z*w2 + c0.w*w3;
                a1 += c1.x*w0 + c1.y*w1 + c1.z*w2 + c1.w*w3;
                a2 += c2.x*w0 + c2.y*w1 + c2.z*w2 + c2.w*w3;
                a3 += c3.x*w0 + c3.y*w1 + c3.z*w2 + c3.w*w3;
            }
            SC.pt[rgrp][0][ecol] = a0;
            SC.pt[rgrp][1][ecol] = a1;
            SC.pt[rgrp][2][ecol] = a2;
            SC.pt[rgrp][3][ecol] = a3;
            BAR_A();

            if (s + 1 < S_) {
                const int np = par ^ 1;
                SC.ks[np][lb][le]     = kf0;
                SC.ks[np][lb + 2][le] = kf1;
                SC.ts[np][lb][le]     = vf0 - kf0;
                SC.ts[np][lb + 2][le] = vf1 - kf1;
                if (s + 2 < S_) {
                    if (((s + 2) & 127) == 0)
                        wait_cnt(&g_ready[(s + 2) >> 7], ready_tgt((s + 2) >> 7));
                    size_t nb = (size_t)((s + 2) * B_ + lb) * E_ + hb + le;
                    kf0 = g_k[nb]; kf1 = g_k[nb + 2 * E_];
                    vf0 = g_v[nb]; vf1 = g_v[nb + 2 * E_];
                }
            }

            // ======== step 1: fused LN1 + bwd1 (one 7-chain reduction) ======
            float z0 = bias0 + SC.pt[0][aw][l]      + SC.pt[1][aw][l];
            float z1 = bias1 + SC.pt[0][aw][l + 32] + SC.pt[1][aw][l + 32];
            float t0 = SC.ts[par][aw][l], t1 = SC.ts[par][aw][l + 32];
            {
                float g0s = g0 * g0, g1s = g1 * g1;
                float w0 = g0 * (bl0 - t0), w1 = g1 * (bl1 - t1);
                float sz   = z0 + z1;
                float szz  = z0*z0 + z1*z1;
                float sg2  = g0s + g1s;
                float sg2z = g0s*z0 + g1s*z1;
                float sg2zz= g0s*z0*z0 + g1s*z1*z1;
                float sw   = w0 + w1;
                float swz  = w0*z0 + w1*z1;
                bfly7(sz, szz, sg2, sg2z, sg2zz, sw, swz);
                float mu   = sz * INV64;
                float rstd = rsqrtf(szz * INV64 - mu*mu + LN_EPS);
                float S1 = C_GRAD * (rstd * (sg2z - mu*sg2) + sw);
                float S2 = C_GRAD * (rstd*rstd * (sg2zz - 2.f*mu*sg2z + mu*mu*sg2)
                                     + rstd * (swz - mu*sw));
                float xh0 = (z0 - mu) * rstd, xh1 = (z1 - mu) * rstd;
                float dp0 = C_GRAD * (xh0*g0 + bl0 - t0);
                float dp1 = C_GRAD * (xh1*g1 + bl1 - t1);
                float dh0 = rstd * (dp0*g0 - (S1 + xh0*S2) * INV64);
                float dh1 = rstd * (dp1*g1 - (S1 + xh1*S2) * INV64);
                SC.d1h[aw][l]          = dh0;
                SC.d1h[aw][l + 32]     = dh1;
                SC.d1x[par][aw][l]      = dp0 * xh0;
                SC.d1x[par][aw][l + 32] = dp1 * xh1;
                SC.d1p[par][aw][l]      = dp0;
                SC.d1p[par][aw][l + 32] = dp1;
            }
            BAR_FULL();                                   // A3

            // ---- param update 1 ----
            {
                float sx0 = SC.d1x[par][0][l] + SC.d1x[par][1][l] + SC.d1x[par][2][l] + SC.d1x[par][3][l];
                float sx1 = SC.d1x[par][0][l+32] + SC.d1x[par][1][l+32] + SC.d1x[par][2][l+32] + SC.d1x[par][3][l+32];
                float sp0 = SC.d1p[par][0][l] + SC.d1p[par][1][l] + SC.d1p[par][2][l] + SC.d1p[par][3][l];
                float sp1 = SC.d1p[par][0][l+32] + SC.d1p[par][1][l+32] + SC.d1p[par][2][l+32] + SC.d1p[par][3][l+32];
                g0 -= LR * sx0; g1 -= LR * sx1;
                bl0 -= LR * sp0; bl1 -= LR * sp1;
            }

            // ---- corr2 ----
            float dh0_1 = SC.d1h[aw][l], dh1_1 = SC.d1h[aw][l + 32];
            {
                float m0 = SC.Ms[aw][0], m1 = SC.Ms[aw][1], m2 = SC.Ms[aw][2], m3 = SC.Ms[aw][3];
                z0 += m0 * SC.d1h[0][l] + m1 * SC.d1h[1][l] + m2 * SC.d1h[2][l] + m3 * SC.d1h[3][l];
                z1 += m0 * SC.d1h[0][l+32] + m1 * SC.d1h[1][l+32] + m2 * SC.d1h[2][l+32] + m3 * SC.d1h[3][l+32];
            }

            // ======== step 2: fused LN2 + bwd2 (one 7-chain reduction) ======
            {
                float g0s = g0 * g0, g1s = g1 * g1;
                float w0 = g0 * (bl0 - t0), w1 = g1 * (bl1 - t1);
                float sz   = z0 + z1;
                float szz  = z0*z0 + z1*z1;
                float sg2  = g0s + g1s;
                float sg2z = g0s*z0 + g1s*z1;
                float sg2zz= g0s*z0*z0 + g1s*z1*z1;
                float sw   = w0 + w1;
                float swz  = w0*z0 + w1*z1;
                bfly7(sz, szz, sg2, sg2z, sg2zz, sw, swz);
                float mu   = sz * INV64;
                float rstd = rsqrtf(szz * INV64 - mu*mu + LN_EPS);
                float S1 = C_GRAD * (rstd * (sg2z - mu*sg2) + sw);
                float S2 = C_GRAD * (rstd*rstd * (sg2zz - 2.f*mu*sg2z + mu*mu*sg2)
                                     + rstd * (swz - mu*sw));
                float xh0 = (z0 - mu) * rstd, xh1 = (z1 - mu) * rstd;
                float dp0 = C_GRAD * (xh0*g0 + bl0 - t0);
                float dp1 = C_GRAD * (xh1*g1 + bl1 - t1);
                float e0 = rstd * (dp0*g0 - (S1 + xh0*S2) * INV64);
                float e1 = rstd * (dp1*g1 - (S1 + xh1*S2) * INV64);

                SC.z2s[aw][l]       = z0;   SC.z2s[aw][l + 32]  = z1;
                SC.d2h[aw][l]       = e0;   SC.d2h[aw][l + 32]  = e1;
                SC.d2x[aw][l]       = dp0 * xh0; SC.d2x[aw][l + 32] = dp1 * xh1;
                SC.d2p[aw][l]       = dp0;  SC.d2p[aw][l + 32]  = dp1;
                SC.dsum[aw][l]      = dh0_1 + e0;
                SC.dsum[aw][l + 32] = dh1_1 + e1;
            }
            BAR_FULL();                                   // S3

            // ---- param update 2 ----
            {
                float sx0 = SC.d2x[0][l] + SC.d2x[1][l] + SC.d2x[2][l] + SC.d2x[3][l];
                float sx1 = SC.d2x[0][l+32] + SC.d2x[1][l+32] + SC.d2x[2][l+32] + SC.d2x[3][l+32];
                float sp0 = SC.d2p[0][l] + SC.d2p[1][l] + SC.d2p[2][l] + SC.d2p[3][l];
                float sp1 = SC.d2p[0][l+32] + SC.d2p[1][l+32] + SC.d2p[2][l+32] + SC.d2p[3][l+32];
                g0 -= LR * sx0; g1 -= LR * sx1;
                bl0 -= LR * sp0; bl1 -= LR * sp1;
                bias0 -= LR * (SC.dsum[0][l] + SC.dsum[1][l] + SC.dsum[2][l] + SC.dsum[3][l]);
                bias1 -= LR * (SC.dsum[0][l+32] + SC.dsum[1][l+32] + SC.dsum[2][l+32] + SC.dsum[3][l+32]);
            }

            // ---- W update ----
            float ds0 = LR * SC.dsum[0][ecol];
            float ds1 = LR * SC.dsum[1][ecol];
            float ds2 = LR * SC.dsum[2][ecol];
            float ds3 = LR * SC.dsum[3][ecol];
#pragma unroll
            for (int i = 0; i < 8; i++) {
                float4 c0 = k40[i], c1 = k41[i], c2 = k42[i], c3 = k43[i];
                Wreg[4*i]   -= c0.x*ds0 + c1.x*ds1 + c2.x*ds2 + c3.x*ds3;
                Wreg[4*i+1] -= c0.y*ds0 + c1.y*ds1 + c2.y*ds2 + c3.y*ds3;
                Wreg[4*i+2] -= c0.z*ds0 + c1.z*ds1 + c2.z*ds2 + c3.z*ds3;
                Wreg[4*i+3] -= c0.w*ds0 + c1.w*ds1 + c2.w*ds2 + c3.w*ds3;
            }
        }
    } else {
        // ================= GROUP B =================
        const int bw = (tid >> 5) - 4;

        float g0  = fw_g[hb + l],  g1  = fw_g[hb + l + 32];
        float bl0 = fw_bl[hb + l], bl1 = fw_bl[hb + l + 32];
        float tg0 = ttt_g[hb + l], tg1 = ttt_g[hb + l + 32];
        float tb0 = ttt_b[hb + l], tb1 = ttt_b[hb + l + 32];

        wait_cnt(&g_ready[0], 192);
        float kk0[4], kk1[4];
#pragma unroll
        for (int b = 0; b < 4; b++) {
            kk0[b] = g_k[(size_t)b * E_ + hb + l];
            kk1[b] = g_k[(size_t)b * E_ + hb + l + 32];
        }
        float Mreg[4];
        {
            float P0 = kk0[bw]*kk0[0] + kk1[bw]*kk1[0];
            float P1 = kk0[bw]*kk0[1] + kk1[bw]*kk1[1];
            float P2 = kk0[bw]*kk0[2] + kk1[bw]*kk1[2];
            float P3 = kk0[bw]*kk0[3] + kk1[bw]*kk1[3];
            bfly4(P0, P1, P2, P3);
            Mreg[0] = -LR * (P0 + 1.0f);
            Mreg[1] = -LR * (P1 + 1.0f);
            Mreg[2] = -LR * (P2 + 1.0f);
            Mreg[3] = -LR * (P3 + 1.0f);
            if (l == 0) {
                SC.Ms[bw][0] = Mreg[0]; SC.Ms[bw][1] = Mreg[1];
                SC.Ms[bw][2] = Mreg[2]; SC.Ms[bw][3] = Mreg[3];
            }
        }
        float q0 = g_q[(size_t)bw * E_ + hb + l];
        float q1 = g_q[(size_t)bw * E_ + hb + l + 32];
#pragma unroll
        for (int b = 0; b < 4; b++) {
            kk0[b] = g_k[(size_t)(1 * B_ + b) * E_ + hb + l];
            kk1[b] = g_k[(size_t)(1 * B_ + b) * E_ + hb + l + 32];
        }

        for (int s = 0; s < S_; s++) {
            BAR_FULL();                                   // A3
            BAR_FULL();                                   // S3
            const int par = s & 1;

            float sx0 = 0.f, sx1 = 0.f, sp0 = 0.f, sp1 = 0.f;
#pragma unroll
            for (int b = 0; b < 4; b++) {
                sx0 += SC.d1x[par][b][l]      + SC.d2x[b][l];
                sx1 += SC.d1x[par][b][l + 32] + SC.d2x[b][l + 32];
                sp0 += SC.d1p[par][b][l]      + SC.d2p[b][l];
                sp1 += SC.d1p[par][b][l + 32] + SC.d2p[b][l + 32];
            }
            g0 -= LR * sx0; g1 -= LR * sx1;
            bl0 -= LR * sp0; bl1 -= LR * sp1;

            float z0 = SC.z2s[bw][l]
                     + Mreg[0]*SC.d2h[0][l] + Mreg[1]*SC.d2h[1][l]
                     + Mreg[2]*SC.d2h[2][l] + Mreg[3]*SC.d2h[3][l];
            float z1 = SC.z2s[bw][l + 32]
                     + Mreg[0]*SC.d2h[0][l+32] + Mreg[1]*SC.d2h[1][l+32]
                     + Mreg[2]*SC.d2h[2][l+32] + Mreg[3]*SC.d2h[3][l+32];

            float sum = z0 + z1, sq = z0 * z0 + z1 * z1;
            bfly2(sum, sq);
            float mu = sum * INV64;
            float rs = rsqrtf(sq * INV64 - mu * mu + LN_EPS);
            float p0 = (z0 - mu) * rs * g0 + bl0;
            float p1 = (z1 - mu) * rs * g1 + bl1;

            sum = p0 + p1; sq = p0 * p0 + p1 * p1;
            bfly2(sum, sq);
            mu = sum * INV64;
            rs = rsqrtf(sq * INV64 - mu * mu + LN_EPS);
            size_t ob = (size_t)(s * B_ + bw) * E_ + hb + l;
            g_scan[ob]      = q0 + (p0 - mu) * rs * tg0 + tb0;
            g_scan[ob + 32] = q1 + (p1 - mu) * rs * tg1 + tb1;

            if ((s & 127) == 127) {
                __threadfence();
                BAR_B();
                if (tid == 128) atomicAdd(&g_scan_done[s >> 7], 1);
            }

            if (s + 1 < S_) {
                float P0 = kk0[bw]*kk0[0] + kk1[bw]*kk1[0];
                float P1 = kk0[bw]*kk0[1] + kk1[bw]*kk1[1];
                float P2 = kk0[bw]*kk0[2] + kk1[bw]*kk1[2];
                float P3 = kk0[bw]*kk0[3] + kk1[bw]*kk1[3];
                bfly4(P0, P1, P2, P3);
                Mreg[0] = -LR * (P0 + 1.0f);
                Mreg[1] = -LR * (P1 + 1.0f);
                Mreg[2] = -LR * (P2 + 1.0f);
                Mreg[3] = -LR * (P3 + 1.0f);
                if (l == 0) {
                    SC.Ms[bw][0] = Mreg[0]; SC.Ms[bw][1] = Mreg[1];
                    SC.Ms[bw][2] = Mreg[2]; SC.Ms[bw][3] = Mreg[3];
                }
                size_t qb = (size_t)((s + 1) * B_ + bw) * E_ + hb + l;
                q0 = g_q[qb];
                q1 = g_q[qb + 32];
                if (s + 2 < S_) {
                    if (((s + 2) & 127) == 0)
                        wait_cnt(&g_ready[(s + 2) >> 7], ready_tgt((s + 2) >> 7));
#pragma unroll
                    for (int b = 0; b < 4; b++) {
                        size_t kb = (size_t)((s + 2) * B_ + b) * E_ + hb + l;
                        kk0[b] = g_k[kb];
                        kk1[b] = g_k[kb + 32];
                    }
                }
            }
        }
    }

    worker_loop(x, Wq, Wk, Wv, Wg, Wo, post_g, post_b, C, U.wk.As, U.wk.Bs, s_tile);
}

__global__ void reset_kernel()
{
    const int t = threadIdx.x;
    if (t < 16) { g_ready[t] = 0; g_gate_ready[t] = 0; g_scan_done[t] = 0; }
    if (t < 64) g_post_done[t] = 0;
    if (t == 64) { g_tile = 0; g_nscan = 0; }
}

extern "C" void kernel_launch(void* const* d_in, const int* in_sizes, int n_in,
                              void* d_out, int out_size)
{
    const float* x      = (const float*)d_in[0];
    const float* Wq     = (const float*)d_in[1];
    const float* Wk     = (const float*)d_in[2];
    const float* Wv     = (const float*)d_in[3];
    const float* Wo     = (const float*)d_in[4];
    const float* Wg     = (const float*)d_in[5];
    const float* fw_W   = (const float*)d_in[6];
    const float* fw_b   = (const float*)d_in[7];
    const float* fw_g   = (const float*)d_in[8];
    const float* fw_bl  = (const float*)d_in[9];
    const float* ttt_g  = (const float*)d_in[10];
    const float* ttt_b  = (const float*)d_in[11];
    const float* post_g = (const float*)d_in[12];
    const float* post_b = (const float*)d_in[13];

    fused_kernel<<<16 + N_WORKERS, 256>>>(x, Wq, Wk, Wv, Wg, Wo,
                                          fw_W, fw_b, fw_g, fw_bl,
                                          ttt_g, ttt_b, post_g, post_b,
                                          (float*)d_out);
    reset_kernel<<<1, 128>>>();
}